// round 13
// baseline (speedup 1.0000x reference)
#include <cuda_runtime.h>
#include <cuda_bf16.h>
#include <math.h>

// Fused FastGuidedFilter, 62x30 tile, packed f32x2 with even/odd split planes.
//   stage 2: packed (sx,sy)/(sxx,sxy) box-stat chains -> A,b ; ALSO keeps the 8
//            im pixels (stage-3 inputs) live in registers.
//   stage 3: packed (A,b) sums; /4-group pre-scaled by 1.5 via fma.f32x2 so all
//            8 candidates share divisor 6 -> single 8-way FMNMX argmin tree.
//   g = (sumA - n)*im + sumB (n-folded) ; val = best/6 + im.
//   out = clip(trunc(best), 0, 255).  hr_x unused by reference.

#define TW 62
#define TH 30
#define SEW 68    // E/O input plane stride in floats (33 pairs = 66 used)
#define SAEW 68   // E/O A-b plane stride in floats (32 pairs = 64 used)

typedef unsigned long long u64;
__device__ __forceinline__ u64 F2ADD(u64 a, u64 b) {
    u64 r; asm("add.rn.f32x2 %0, %1, %2;" : "=l"(r) : "l"(a), "l"(b)); return r;
}
__device__ __forceinline__ u64 F2MUL(u64 a, u64 b) {
    u64 r; asm("mul.rn.f32x2 %0, %1, %2;" : "=l"(r) : "l"(a), "l"(b)); return r;
}
__device__ __forceinline__ u64 F2FMA(u64 a, u64 b, u64 c) {
    u64 r; asm("fma.rn.f32x2 %0, %1, %2, %3;" : "=l"(r) : "l"(a), "l"(b), "l"(c)); return r;
}
__device__ __forceinline__ u64 F2PK(float a, float b) {
    u64 r; asm("mov.b64 %0, {%1, %2};" : "=l"(r) : "f"(a), "f"(b)); return r;
}
__device__ __forceinline__ void F2UP(u64 v, float& a, float& b) {
    asm("mov.b64 {%0, %1}, %2;" : "=f"(a), "=f"(b) : "l"(v));
}
__device__ __forceinline__ float F2LO(u64 v) {
    float a, b; asm("mov.b64 {%0, %1}, %2;" : "=f"(a), "=f"(b) : "l"(v)); return a;
}
__device__ __forceinline__ u64 F2DUPLO(u64 v) {
    u64 r;
    asm("{ .reg .f32 lo, hi;\n\t"
        "  mov.b64 {lo, hi}, %1;\n\t"
        "  mov.b64 %0, {lo, lo}; }"
        : "=l"(r) : "l"(v));
    return r;
}

// All candidates share divisor 6 (the /4 group is pre-scaled by 1.5).
__device__ __forceinline__ void emit_row(
    const u64 hL[5], const u64 hT[5], const u64 hB[5],
    const u64 hU[4], const u64 hD[4],
    const float imv[4], float res[4])
{
    #pragma unroll
    for (int vc = 0; vc < 4; ++vc) {
        const float im = imv[vc];
        float a, b;
        // reference order L,R,U,D,NW,NE,SW,SE
        F2UP(hL[vc],   a, b); float c0 = fmaf(a, im, b);   // L
        F2UP(hL[vc+1], a, b); float c1 = fmaf(a, im, b);   // R
        F2UP(hU[vc],   a, b); float c2 = fmaf(a, im, b);   // U
        F2UP(hD[vc],   a, b); float c3 = fmaf(a, im, b);   // D
        F2UP(hT[vc],   a, b); float c4 = fmaf(a, im, b);   // NW (x1.5)
        F2UP(hT[vc+1], a, b); float c5 = fmaf(a, im, b);   // NE (x1.5)
        F2UP(hB[vc],   a, b); float c6 = fmaf(a, im, b);   // SW (x1.5)
        F2UP(hB[vc+1], a, b); float c7 = fmaf(a, im, b);   // SE (x1.5)

        float e0 = fabsf(c0), e1 = fabsf(c1), e2 = fabsf(c2), e3 = fabsf(c3);
        float e4 = fabsf(c4), e5 = fabsf(c5), e6 = fabsf(c6), e7 = fabsf(c7);
        float d = fminf(fminf(fminf(e0, e1), fminf(e2, e3)),
                        fminf(fminf(e4, e5), fminf(e6, e7)));
        float best = (e0 == d) ? c0 : (e1 == d) ? c1 : (e2 == d) ? c2 :
                     (e3 == d) ? c3 : (e4 == d) ? c4 : (e5 == d) ? c5 :
                     (e6 == d) ? c6 : c7;   // first-min wins (jnp.argmin order)

        float val = fmaf(best, 1.0f / 6.0f, im);
        res[vc] = fminf(fmaxf(truncf(val), 0.0f), 255.0f);
    }
}

__global__ __launch_bounds__(256, 4)
void fgf_kernel(const float* __restrict__ lrx,
                const float* __restrict__ lry,
                float* __restrict__ out,
                int H, int W)
{
    __shared__ __align__(16) float sxyE[34 * SEW];   // (x,y) pairs, even cols
    __shared__ __align__(16) float sxyO[34 * SEW];   // (x,y) pairs, odd cols
    __shared__ __align__(16) float sabE[32 * SAEW];  // (A,b) pairs, even cols
    __shared__ __align__(16) float sabO[32 * SAEW];  // (A,b) pairs, odd cols

    const int tid = threadIdx.x;
    const int c   = blockIdx.z;
    const int gx0 = blockIdx.x * TW;
    const int gy0 = blockIdx.y * TH;
    const float* __restrict__ px = lrx + (size_t)c * H * W;
    const float* __restrict__ py = lry + (size_t)c * H * W;

    const bool xin = (gx0 >= 2) && (gx0 + TW + 2 <= W);
    const bool yin = (gy0 >= 2) && (gy0 + TH + 2 <= H);
    const bool inner = xin && yin;

    // ---- stage 1: load 34x66 halo tile into (x,y) even/odd planes ----
    if (xin) {
        const int warp = tid >> 5;
        const int lane = tid & 31;
        #pragma unroll
        for (int it = 0; it < 4; ++it) {
            int r  = warp + it * 8;
            int gy = gy0 + r - 2; gy = max(0, min(H - 1, gy));
            const float* rowx = px + (size_t)gy * W + (gx0 - 2);
            const float* rowy = py + (size_t)gy * W + (gx0 - 2);
            float2 vx = *(const float2*)(rowx + lane * 2);
            float2 vy = *(const float2*)(rowy + lane * 2);
            *(float2*)&sxyE[r * SEW + lane * 2] = make_float2(vx.x, vy.x);
            *(float2*)&sxyO[r * SEW + lane * 2] = make_float2(vx.y, vy.y);
            if (lane == 31) {   // 33rd pair: cols 64,65
                float2 wx = *(const float2*)(rowx + 64);
                float2 wy = *(const float2*)(rowy + 64);
                *(float2*)&sxyE[r * SEW + 64] = make_float2(wx.x, wy.x);
                *(float2*)&sxyO[r * SEW + 64] = make_float2(wx.y, wy.y);
            }
        }
        if (warp < 2) {
            int r  = 32 + warp;
            int gy = gy0 + r - 2; gy = max(0, min(H - 1, gy));
            const float* rowx = px + (size_t)gy * W + (gx0 - 2);
            const float* rowy = py + (size_t)gy * W + (gx0 - 2);
            float2 vx = *(const float2*)(rowx + lane * 2);
            float2 vy = *(const float2*)(rowy + lane * 2);
            *(float2*)&sxyE[r * SEW + lane * 2] = make_float2(vx.x, vy.x);
            *(float2*)&sxyO[r * SEW + lane * 2] = make_float2(vx.y, vy.y);
            if (lane == 31) {
                float2 wx = *(const float2*)(rowx + 64);
                float2 wy = *(const float2*)(rowy + 64);
                *(float2*)&sxyE[r * SEW + 64] = make_float2(wx.x, wy.x);
                *(float2*)&sxyO[r * SEW + 64] = make_float2(wx.y, wy.y);
            }
        }
    } else {
        for (int i = tid; i < 34 * 66; i += 256) {
            int r = i / 66;
            int q = i - r * 66;
            int gy = gy0 + r - 2; gy = max(0, min(H - 1, gy));
            int gx = gx0 + q - 2; gx = max(0, min(W - 1, gx));
            size_t g = (size_t)gy * W + gx;
            float* plane = (q & 1) ? sxyO : sxyE;
            int off = r * SEW + (q & ~1);
            plane[off]     = px[g];
            plane[off + 1] = py[g];
        }
    }
    __syncthreads();

    // im pixels for stage 3 (same thread mapping: (cr,cq) == (ty,tx))
    float im0[4], im1[4];

    // ---- stage 2: A,b on exact 32x64 grid, one 2x4 chunk per thread, packed stats ----
    {
        const int cr = tid >> 4;          // 0..15
        const int cq = tid & 15;          // 0..15
        const int r0 = cr * 2, q0 = cq * 4;
        const int fo = cq * 4;            // float offset in E/O planes

        u64 S0p[4], S0m[4], S1p[4], S1m[4];   // p=(sx,sy), m=(sxx,sxy)

        #pragma unroll
        for (int u = 0; u < 4; ++u) {
            const float* eb = &sxyE[(r0 + u) * SEW + fo];
            const float* ob = &sxyO[(r0 + u) * SEW + fo];
            ulonglong2 eL = *(const ulonglong2*)eb;
            u64 e2 = *(const u64*)(eb + 4);
            ulonglong2 oL = *(const ulonglong2*)ob;
            u64 o2 = *(const u64*)(ob + 4);
            u64 p[6] = { eL.x, oL.x, eL.y, oL.y, e2, o2 };   // cols q0..q0+5

            // keep im pixels: input rows r0+2, r0+3 = output rows oy0, oy0+1;
            // cols q0+2..q0+5 = ox0+2..ox0+5
            if (u == 2) { im0[0] = F2LO(p[2]); im0[1] = F2LO(p[3]); im0[2] = F2LO(p[4]); im0[3] = F2LO(p[5]); }
            if (u == 3) { im1[0] = F2LO(p[2]); im1[1] = F2LO(p[3]); im1[2] = F2LO(p[4]); im1[3] = F2LO(p[5]); }

            u64 m[6];
            #pragma unroll
            for (int v = 0; v < 6; ++v)
                m[v] = F2MUL(F2DUPLO(p[v]), p[v]);           // (x*x, x*y)

            u64 hp[4], hm[4];
            #pragma unroll
            for (int d = 0; d < 4; ++d) {
                hp[d] = F2ADD(F2ADD(p[d], p[d + 1]), p[d + 2]);
                hm[d] = F2ADD(F2ADD(m[d], m[d + 1]), m[d + 2]);
            }

            if (u == 0) {
                #pragma unroll
                for (int d = 0; d < 4; ++d) { S0p[d] = hp[d]; S0m[d] = hm[d]; }
            } else if (u == 1) {
                #pragma unroll
                for (int d = 0; d < 4; ++d) {
                    S0p[d] = F2ADD(S0p[d], hp[d]); S0m[d] = F2ADD(S0m[d], hm[d]);
                    S1p[d] = hp[d];                S1m[d] = hm[d];
                }
            } else if (u == 2) {
                #pragma unroll
                for (int d = 0; d < 4; ++d) {
                    S0p[d] = F2ADD(S0p[d], hp[d]); S0m[d] = F2ADD(S0m[d], hm[d]);
                    S1p[d] = F2ADD(S1p[d], hp[d]); S1m[d] = F2ADD(S1m[d], hm[d]);
                }
            } else {
                #pragma unroll
                for (int d = 0; d < 4; ++d) {
                    S1p[d] = F2ADD(S1p[d], hp[d]); S1m[d] = F2ADD(S1m[d], hm[d]);
                }
            }
        }

        #pragma unroll
        for (int dr = 0; dr < 2; ++dr) {
            float Ao[4], Bo[4];
            #pragma unroll
            for (int dc = 0; dc < 4; ++dc) {
                float sxv, syv, sxx, sxy_;
                F2UP(dr ? S1p[dc] : S0p[dc], sxv, syv);
                F2UP(dr ? S1m[dc] : S0m[dc], sxx, sxy_);
                // A = (sxy - sx*sy/9)/(sxx - sx*sx/9 + 9*eps); b = (sy - A*sx)/9
                float t   = sxv * (-1.0f / 9.0f);
                float num = fmaf(t, syv, sxy_);
                float den = fmaf(t, sxv, sxx) + 9e-4f;
                float A = __fdividef(num, den);
                float B = (syv - A * sxv) * (1.0f / 9.0f);
                if (!inner) {
                    int gy = gy0 + r0 + dr - 1;
                    int gx = gx0 + q0 + dc - 1;
                    if (gy < 0 || gy >= H || gx < 0 || gx >= W) { A = 0.0f; B = 0.0f; }
                }
                Ao[dc] = A; Bo[dc] = B;
            }
            *(float4*)&sabE[(r0 + dr) * SAEW + fo] = make_float4(Ao[0], Bo[0], Ao[2], Bo[2]);
            *(float4*)&sabO[(r0 + dr) * SAEW + fo] = make_float4(Ao[1], Bo[1], Ao[3], Bo[3]);
        }
    }
    __syncthreads();

    // ---- stage 3: packed (A,b) sums + cross-row reuse + unified argmin ----
    const int maxy = min(TH, H - gy0);
    const int maxx = min(TW, W - gx0);
    const int ty  = tid >> 4;        // 0..15
    const int tx  = tid & 15;        // 0..15
    const int oy0 = ty * 2, ox0 = tx * 4;
    const int fo  = tx * 4;          // float offset in E/O planes

    if (oy0 >= maxy || ox0 >= maxx) return;   // no syncs after this point

    float* __restrict__ po = out + (size_t)c * H * W;

    #define LOADAB(C, row) { \
        const float* e_ = &sabE[(row) * SAEW + fo]; \
        const float* o_ = &sabO[(row) * SAEW + fo]; \
        ulonglong2 eL_ = *(const ulonglong2*)e_; \
        ulonglong2 oL_ = *(const ulonglong2*)o_; \
        C[0] = eL_.x; C[1] = oL_.x; C[2] = eL_.y; C[3] = oL_.y; \
        C[4] = *(const u64*)(e_ + 4); C[5] = *(const u64*)(o_ + 4); }

    #define STOREROW(oy, res) { \
        float* prow = po + (size_t)(gy0 + (oy)) * W + (gx0 + ox0); \
        if (ox0 + 4 <= maxx) { \
            *(float2*)prow       = make_float2(res[0], res[1]); \
            *(float2*)(prow + 2) = make_float2(res[2], res[3]); \
        } else { \
            _Pragma("unroll") \
            for (int vc = 0; vc < 4; ++vc) \
                if (ox0 + vc < maxx) prow[vc] = res[vc]; \
        } }

    const u64 C6  = F2PK(-6.0f, 0.0f);
    const u64 K15 = F2PK(1.5f, 1.5f);

    u64 vpB[6];                    // bottom vertical pairs (live into row1)
    u64 hB[5], hD[4];              // bottom h-sums (renamed into row1's top)
    {
        u64 R0[6], R1[6], R2[6];
        LOADAB(R0, oy0);
        LOADAB(R1, oy0 + 1);
        LOADAB(R2, oy0 + 2);

        u64 vpT[6], vt[6];
        #pragma unroll
        for (int v = 0; v < 6; ++v) {
            vpT[v] = F2ADD(R0[v], R1[v]);
            vpB[v] = F2ADD(R1[v], R2[v]);
            vt[v]  = F2ADD(vpT[v], R2[v]);
        }

        u64 hL[5], hT[5], hU[4];
        #pragma unroll
        for (int q = 0; q < 5; ++q) {
            u64 psT = F2ADD(vpT[q], vpT[q + 1]);
            u64 psB = F2ADD(vpB[q], vpB[q + 1]);
            hL[q] = F2ADD(F2ADD(vt[q], vt[q + 1]), C6);
            hT[q] = F2FMA(psT, K15, C6);                 // scaled /4 group
            hB[q] = F2FMA(psB, K15, C6);
            if (q < 4) {
                hU[q] = F2ADD(F2ADD(psT, vpT[q + 2]), C6);   // unscaled triple
                hD[q] = F2ADD(F2ADD(psB, vpB[q + 2]), C6);
            }
        }

        float res[4];
        emit_row(hL, hT, hB, hU, hD, im0, res);
        STOREROW(oy0, res);
    }

    // ---- row 1 (reuses: hT = row0's hB, hU = row0's hD; vpT = row0's vpB) ----
    if (oy0 + 1 < maxy) {
        u64 R2[6], R3[6];
        LOADAB(R2, oy0 + 2);
        LOADAB(R3, oy0 + 3);

        u64 vpB1[6], vt1[6];
        #pragma unroll
        for (int v = 0; v < 6; ++v) {
            vpB1[v] = F2ADD(R2[v], R3[v]);
            vt1[v]  = F2ADD(vpB[v], R3[v]);   // vpT(row1) == vpB(row0)
        }

        u64 hL1[5], hB1[5], hD1[4];
        #pragma unroll
        for (int q = 0; q < 5; ++q) {
            u64 psB1 = F2ADD(vpB1[q], vpB1[q + 1]);
            hL1[q] = F2ADD(F2ADD(vt1[q], vt1[q + 1]), C6);
            hB1[q] = F2FMA(psB1, K15, C6);
            if (q < 4)
                hD1[q] = F2ADD(F2ADD(psB1, vpB1[q + 2]), C6);
        }

        float res[4];
        // hT(row1)=hB(row0) [scaled], hU(row1)=hD(row0)
        emit_row(hL1, hB, hB1, hD, hD1, im1, res);
        STOREROW(oy0 + 1, res);
    }
    #undef LOADAB
    #undef STOREROW
}

extern "C" void kernel_launch(void* const* d_in, const int* in_sizes, int n_in,
                              void* d_out, int out_size)
{
    const float* lrx = (const float*)d_in[0];
    const float* lry = (const float*)d_in[1];
    // d_in[2] (hr_x) is unused by the reference computation.
    float* out = (float*)d_out;

    const int H = 2048, W = 2048;
    dim3 block(256);
    dim3 grid((W + TW - 1) / TW, (H + TH - 1) / TH, 3);
    fgf_kernel<<<grid, block>>>(lrx, lry, out, H, W);
}

// round 14
// speedup vs baseline: 1.1936x; 1.1936x over previous
#include <cuda_runtime.h>
#include <cuda_bf16.h>
#include <math.h>

// Fused FastGuidedFilter, 62x30 tile, packed f32x2 with even/odd split planes.
//   stage 2: packed (sx,sy)/(sxx,sxy) box-stat chains -> A,b (no cross-sync regs)
//   stage 3: packed (A,b) sums; /4-group pre-scaled by 1.5 via fma.f32x2 so all
//            8 candidates share divisor 6 -> single 8-way FMNMX argmin tree.
//            im read from smem (NOT kept in registers across the sync - spills).
//   out = clip(trunc(best/6 + im), 0, 255).  hr_x unused by reference.

#define TW 62
#define TH 30
#define SEW 68    // E/O input plane stride in floats (33 pairs = 66 used)
#define SAEW 68   // E/O A-b plane stride in floats (32 pairs = 64 used)

typedef unsigned long long u64;
__device__ __forceinline__ u64 F2ADD(u64 a, u64 b) {
    u64 r; asm("add.rn.f32x2 %0, %1, %2;" : "=l"(r) : "l"(a), "l"(b)); return r;
}
__device__ __forceinline__ u64 F2MUL(u64 a, u64 b) {
    u64 r; asm("mul.rn.f32x2 %0, %1, %2;" : "=l"(r) : "l"(a), "l"(b)); return r;
}
__device__ __forceinline__ u64 F2FMA(u64 a, u64 b, u64 c) {
    u64 r; asm("fma.rn.f32x2 %0, %1, %2, %3;" : "=l"(r) : "l"(a), "l"(b), "l"(c)); return r;
}
__device__ __forceinline__ u64 F2PK(float a, float b) {
    u64 r; asm("mov.b64 %0, {%1, %2};" : "=l"(r) : "f"(a), "f"(b)); return r;
}
__device__ __forceinline__ void F2UP(u64 v, float& a, float& b) {
    asm("mov.b64 {%0, %1}, %2;" : "=f"(a), "=f"(b) : "l"(v));
}
__device__ __forceinline__ u64 F2DUPLO(u64 v) {
    u64 r;
    asm("{ .reg .f32 lo, hi;\n\t"
        "  mov.b64 {lo, hi}, %1;\n\t"
        "  mov.b64 %0, {lo, lo}; }"
        : "=l"(r) : "l"(v));
    return r;
}

// All candidates share divisor 6 (the /4 group was pre-scaled by 1.5).
__device__ __forceinline__ void emit_row(
    const u64 hL[5], const u64 hT[5], const u64 hB[5],
    const u64 hU[4], const u64 hD[4],
    const float imv[4], float res[4])
{
    #pragma unroll
    for (int vc = 0; vc < 4; ++vc) {
        const float im = imv[vc];
        float a, b;
        // reference order L,R,U,D,NW,NE,SW,SE
        F2UP(hL[vc],   a, b); float c0 = fmaf(a, im, b);   // L
        F2UP(hL[vc+1], a, b); float c1 = fmaf(a, im, b);   // R
        F2UP(hU[vc],   a, b); float c2 = fmaf(a, im, b);   // U
        F2UP(hD[vc],   a, b); float c3 = fmaf(a, im, b);   // D
        F2UP(hT[vc],   a, b); float c4 = fmaf(a, im, b);   // NW (x1.5)
        F2UP(hT[vc+1], a, b); float c5 = fmaf(a, im, b);   // NE (x1.5)
        F2UP(hB[vc],   a, b); float c6 = fmaf(a, im, b);   // SW (x1.5)
        F2UP(hB[vc+1], a, b); float c7 = fmaf(a, im, b);   // SE (x1.5)

        float e0 = fabsf(c0), e1 = fabsf(c1), e2 = fabsf(c2), e3 = fabsf(c3);
        float e4 = fabsf(c4), e5 = fabsf(c5), e6 = fabsf(c6), e7 = fabsf(c7);
        float d = fminf(fminf(fminf(e0, e1), fminf(e2, e3)),
                        fminf(fminf(e4, e5), fminf(e6, e7)));
        float best = (e0 == d) ? c0 : (e1 == d) ? c1 : (e2 == d) ? c2 :
                     (e3 == d) ? c3 : (e4 == d) ? c4 : (e5 == d) ? c5 :
                     (e6 == d) ? c6 : c7;   // first-min wins (jnp.argmin order)

        float val = fmaf(best, 1.0f / 6.0f, im);
        res[vc] = fminf(fmaxf(truncf(val), 0.0f), 255.0f);
    }
}

__global__ __launch_bounds__(256, 4)
void fgf_kernel(const float* __restrict__ lrx,
                const float* __restrict__ lry,
                float* __restrict__ out,
                int H, int W)
{
    __shared__ __align__(16) float sxyE[34 * SEW];   // (x,y) pairs, even cols
    __shared__ __align__(16) float sxyO[34 * SEW];   // (x,y) pairs, odd cols
    __shared__ __align__(16) float sabE[32 * SAEW];  // (A,b) pairs, even cols
    __shared__ __align__(16) float sabO[32 * SAEW];  // (A,b) pairs, odd cols

    const int tid = threadIdx.x;
    const int c   = blockIdx.z;
    const int gx0 = blockIdx.x * TW;
    const int gy0 = blockIdx.y * TH;
    const float* __restrict__ px = lrx + (size_t)c * H * W;
    const float* __restrict__ py = lry + (size_t)c * H * W;

    const bool xin = (gx0 >= 2) && (gx0 + TW + 2 <= W);
    const bool yin = (gy0 >= 2) && (gy0 + TH + 2 <= H);
    const bool inner = xin && yin;

    // ---- stage 1: load 34x66 halo tile into (x,y) even/odd planes ----
    if (xin) {
        const int warp = tid >> 5;
        const int lane = tid & 31;
        #pragma unroll
        for (int it = 0; it < 4; ++it) {
            int r  = warp + it * 8;
            int gy = gy0 + r - 2; gy = max(0, min(H - 1, gy));
            const float* rowx = px + (size_t)gy * W + (gx0 - 2);
            const float* rowy = py + (size_t)gy * W + (gx0 - 2);
            float2 vx = *(const float2*)(rowx + lane * 2);
            float2 vy = *(const float2*)(rowy + lane * 2);
            *(float2*)&sxyE[r * SEW + lane * 2] = make_float2(vx.x, vy.x);
            *(float2*)&sxyO[r * SEW + lane * 2] = make_float2(vx.y, vy.y);
            if (lane == 31) {   // 33rd pair: cols 64,65
                float2 wx = *(const float2*)(rowx + 64);
                float2 wy = *(const float2*)(rowy + 64);
                *(float2*)&sxyE[r * SEW + 64] = make_float2(wx.x, wy.x);
                *(float2*)&sxyO[r * SEW + 64] = make_float2(wx.y, wy.y);
            }
        }
        if (warp < 2) {
            int r  = 32 + warp;
            int gy = gy0 + r - 2; gy = max(0, min(H - 1, gy));
            const float* rowx = px + (size_t)gy * W + (gx0 - 2);
            const float* rowy = py + (size_t)gy * W + (gx0 - 2);
            float2 vx = *(const float2*)(rowx + lane * 2);
            float2 vy = *(const float2*)(rowy + lane * 2);
            *(float2*)&sxyE[r * SEW + lane * 2] = make_float2(vx.x, vy.x);
            *(float2*)&sxyO[r * SEW + lane * 2] = make_float2(vx.y, vy.y);
            if (lane == 31) {
                float2 wx = *(const float2*)(rowx + 64);
                float2 wy = *(const float2*)(rowy + 64);
                *(float2*)&sxyE[r * SEW + 64] = make_float2(wx.x, wy.x);
                *(float2*)&sxyO[r * SEW + 64] = make_float2(wx.y, wy.y);
            }
        }
    } else {
        for (int i = tid; i < 34 * 66; i += 256) {
            int r = i / 66;
            int q = i - r * 66;
            int gy = gy0 + r - 2; gy = max(0, min(H - 1, gy));
            int gx = gx0 + q - 2; gx = max(0, min(W - 1, gx));
            size_t g = (size_t)gy * W + gx;
            float* plane = (q & 1) ? sxyO : sxyE;
            int off = r * SEW + (q & ~1);
            plane[off]     = px[g];
            plane[off + 1] = py[g];
        }
    }
    __syncthreads();

    // ---- stage 2: A,b on exact 32x64 grid, one 2x4 chunk per thread, packed stats ----
    {
        const int cr = tid >> 4;          // 0..15
        const int cq = tid & 15;          // 0..15
        const int r0 = cr * 2, q0 = cq * 4;
        const int fo = cq * 4;            // float offset in E/O planes

        u64 S0p[4], S0m[4], S1p[4], S1m[4];   // p=(sx,sy), m=(sxx,sxy)

        #pragma unroll
        for (int u = 0; u < 4; ++u) {
            const float* eb = &sxyE[(r0 + u) * SEW + fo];
            const float* ob = &sxyO[(r0 + u) * SEW + fo];
            ulonglong2 eL = *(const ulonglong2*)eb;
            u64 e2 = *(const u64*)(eb + 4);
            ulonglong2 oL = *(const ulonglong2*)ob;
            u64 o2 = *(const u64*)(ob + 4);
            u64 p[6] = { eL.x, oL.x, eL.y, oL.y, e2, o2 };   // cols q0..q0+5

            u64 m[6];
            #pragma unroll
            for (int v = 0; v < 6; ++v)
                m[v] = F2MUL(F2DUPLO(p[v]), p[v]);           // (x*x, x*y)

            u64 hp[4], hm[4];
            #pragma unroll
            for (int d = 0; d < 4; ++d) {
                hp[d] = F2ADD(F2ADD(p[d], p[d + 1]), p[d + 2]);
                hm[d] = F2ADD(F2ADD(m[d], m[d + 1]), m[d + 2]);
            }

            if (u == 0) {
                #pragma unroll
                for (int d = 0; d < 4; ++d) { S0p[d] = hp[d]; S0m[d] = hm[d]; }
            } else if (u == 1) {
                #pragma unroll
                for (int d = 0; d < 4; ++d) {
                    S0p[d] = F2ADD(S0p[d], hp[d]); S0m[d] = F2ADD(S0m[d], hm[d]);
                    S1p[d] = hp[d];                S1m[d] = hm[d];
                }
            } else if (u == 2) {
                #pragma unroll
                for (int d = 0; d < 4; ++d) {
                    S0p[d] = F2ADD(S0p[d], hp[d]); S0m[d] = F2ADD(S0m[d], hm[d]);
                    S1p[d] = F2ADD(S1p[d], hp[d]); S1m[d] = F2ADD(S1m[d], hm[d]);
                }
            } else {
                #pragma unroll
                for (int d = 0; d < 4; ++d) {
                    S1p[d] = F2ADD(S1p[d], hp[d]); S1m[d] = F2ADD(S1m[d], hm[d]);
                }
            }
        }

        #pragma unroll
        for (int dr = 0; dr < 2; ++dr) {
            float Ao[4], Bo[4];
            #pragma unroll
            for (int dc = 0; dc < 4; ++dc) {
                float sxv, syv, sxx, sxy_;
                F2UP(dr ? S1p[dc] : S0p[dc], sxv, syv);
                F2UP(dr ? S1m[dc] : S0m[dc], sxx, sxy_);
                // A = (sxy - sx*sy/9)/(sxx - sx*sx/9 + 9*eps); b = (sy - A*sx)/9
                float t   = sxv * (-1.0f / 9.0f);
                float num = fmaf(t, syv, sxy_);
                float den = fmaf(t, sxv, sxx) + 9e-4f;
                float A = __fdividef(num, den);
                float B = (syv - A * sxv) * (1.0f / 9.0f);
                if (!inner) {
                    int gy = gy0 + r0 + dr - 1;
                    int gx = gx0 + q0 + dc - 1;
                    if (gy < 0 || gy >= H || gx < 0 || gx >= W) { A = 0.0f; B = 0.0f; }
                }
                Ao[dc] = A; Bo[dc] = B;
            }
            *(float4*)&sabE[(r0 + dr) * SAEW + fo] = make_float4(Ao[0], Bo[0], Ao[2], Bo[2]);
            *(float4*)&sabO[(r0 + dr) * SAEW + fo] = make_float4(Ao[1], Bo[1], Ao[3], Bo[3]);
        }
    }
    __syncthreads();

    // ---- stage 3: packed (A,b) sums + cross-row reuse + unified argmin ----
    const int maxy = min(TH, H - gy0);
    const int maxx = min(TW, W - gx0);
    const int ty  = tid >> 4;        // 0..15
    const int tx  = tid & 15;        // 0..15
    const int oy0 = ty * 2, ox0 = tx * 4;
    const int fo  = tx * 4;          // float offset in E/O planes

    if (oy0 >= maxy || ox0 >= maxx) return;   // no syncs after this point

    float* __restrict__ po = out + (size_t)c * H * W;

    #define LOADAB(C, row) { \
        const float* e_ = &sabE[(row) * SAEW + fo]; \
        const float* o_ = &sabO[(row) * SAEW + fo]; \
        ulonglong2 eL_ = *(const ulonglong2*)e_; \
        ulonglong2 oL_ = *(const ulonglong2*)o_; \
        C[0] = eL_.x; C[1] = oL_.x; C[2] = eL_.y; C[3] = oL_.y; \
        C[4] = *(const u64*)(e_ + 4); C[5] = *(const u64*)(o_ + 4); }

    #define STOREROW(oy, res) { \
        float* prow = po + (size_t)(gy0 + (oy)) * W + (gx0 + ox0); \
        if (ox0 + 4 <= maxx) { \
            *(float2*)prow       = make_float2(res[0], res[1]); \
            *(float2*)(prow + 2) = make_float2(res[2], res[3]); \
        } else { \
            _Pragma("unroll") \
            for (int vc = 0; vc < 4; ++vc) \
                if (ox0 + vc < maxx) prow[vc] = res[vc]; \
        } }

    // im values for output row oy: x components at cols ox0+2..ox0+5 (from smem)
    #define LOADIM(imv, oy) { \
        const float* e_ = &sxyE[((oy) + 2) * SEW + fo + 2]; \
        const float* o_ = &sxyO[((oy) + 2) * SEW + fo + 2]; \
        imv[0] = ((const float2*)e_)->x; \
        imv[1] = ((const float2*)o_)->x; \
        imv[2] = ((const float2*)(e_ + 2))->x; \
        imv[3] = ((const float2*)(o_ + 2))->x; }

    const u64 C6  = F2PK(-6.0f, 0.0f);
    const u64 K15 = F2PK(1.5f, 1.5f);

    u64 vpB[6];                    // bottom vertical pairs (live into row1)
    u64 hB[5], hD[4];              // bottom h-sums (renamed into row1's top)
    {
        u64 R0[6], R1[6], R2[6];
        LOADAB(R0, oy0);
        LOADAB(R1, oy0 + 1);
        LOADAB(R2, oy0 + 2);

        u64 vpT[6], vt[6];
        #pragma unroll
        for (int v = 0; v < 6; ++v) {
            vpT[v] = F2ADD(R0[v], R1[v]);
            vpB[v] = F2ADD(R1[v], R2[v]);
            vt[v]  = F2ADD(vpT[v], R2[v]);
        }

        u64 hL[5], hT[5], hU[4];
        #pragma unroll
        for (int q = 0; q < 5; ++q) {
            u64 psT = F2ADD(vpT[q], vpT[q + 1]);
            u64 psB = F2ADD(vpB[q], vpB[q + 1]);
            hL[q] = F2ADD(F2ADD(vt[q], vt[q + 1]), C6);
            hT[q] = F2FMA(psT, K15, C6);                 // scaled /4 group
            hB[q] = F2FMA(psB, K15, C6);
            if (q < 4) {
                hU[q] = F2ADD(F2ADD(psT, vpT[q + 2]), C6);   // unscaled triple
                hD[q] = F2ADD(F2ADD(psB, vpB[q + 2]), C6);
            }
        }

        float imv[4], res[4];
        LOADIM(imv, oy0);
        emit_row(hL, hT, hB, hU, hD, imv, res);
        STOREROW(oy0, res);
    }

    // ---- row 1 (reuses: hT = row0's hB [scaled], hU = row0's hD; vpT = row0's vpB) ----
    if (oy0 + 1 < maxy) {
        u64 R2[6], R3[6];
        LOADAB(R2, oy0 + 2);
        LOADAB(R3, oy0 + 3);

        u64 vpB1[6], vt1[6];
        #pragma unroll
        for (int v = 0; v < 6; ++v) {
            vpB1[v] = F2ADD(R2[v], R3[v]);
            vt1[v]  = F2ADD(vpB[v], R3[v]);   // vpT(row1) == vpB(row0)
        }

        u64 hL1[5], hB1[5], hD1[4];
        #pragma unroll
        for (int q = 0; q < 5; ++q) {
            u64 psB1 = F2ADD(vpB1[q], vpB1[q + 1]);
            hL1[q] = F2ADD(F2ADD(vt1[q], vt1[q + 1]), C6);
            hB1[q] = F2FMA(psB1, K15, C6);
            if (q < 4)
                hD1[q] = F2ADD(F2ADD(psB1, vpB1[q + 2]), C6);
        }

        float imv[4], res[4];
        LOADIM(imv, oy0 + 1);
        emit_row(hL1, hB, hB1, hD, hD1, imv, res);
        STOREROW(oy0 + 1, res);
    }
    #undef LOADAB
    #undef STOREROW
    #undef LOADIM
}

extern "C" void kernel_launch(void* const* d_in, const int* in_sizes, int n_in,
                              void* d_out, int out_size)
{
    const float* lrx = (const float*)d_in[0];
    const float* lry = (const float*)d_in[1];
    // d_in[2] (hr_x) is unused by the reference computation.
    float* out = (float*)d_out;

    const int H = 2048, W = 2048;
    dim3 block(256);
    dim3 grid((W + TW - 1) / TW, (H + TH - 1) / TH, 3);
    fgf_kernel<<<grid, block>>>(lrx, lry, out, H, W);
}

// round 15
// speedup vs baseline: 1.6584x; 1.3894x over previous
#include <cuda_runtime.h>
#include <cuda_bf16.h>
#include <math.h>

// Fused FastGuidedFilter, 62x30 tile, packed f32x2 with even/odd split planes.
//   stage 2: packed (sx,sy)/(sxx,sxy) box-stat chains -> A,b ; inner/edge blocks
//            take a uniform branch (no per-element bounds math on the hot path).
//   stage 3: packed (A,b) vertical+horizontal sums, shift consts folded,
//            cross-row reuse, FMNMX-tree grouped argmin (two groups, R12 form).
//   g = (sumA - n)*im + sumB ; cross-group 3|g4| < 2|g6|.
//   out = clip(trunc(best), 0, 255).  hr_x unused by reference.

#define TW 62
#define TH 30
#define SEW 68    // E/O input plane stride in floats (33 pairs = 66 used)
#define SAEW 68   // E/O A-b plane stride in floats (32 pairs = 64 used)

typedef unsigned long long u64;
__device__ __forceinline__ u64 F2ADD(u64 a, u64 b) {
    u64 r; asm("add.rn.f32x2 %0, %1, %2;" : "=l"(r) : "l"(a), "l"(b)); return r;
}
__device__ __forceinline__ u64 F2MUL(u64 a, u64 b) {
    u64 r; asm("mul.rn.f32x2 %0, %1, %2;" : "=l"(r) : "l"(a), "l"(b)); return r;
}
__device__ __forceinline__ u64 F2PK(float a, float b) {
    u64 r; asm("mov.b64 %0, {%1, %2};" : "=l"(r) : "f"(a), "f"(b)); return r;
}
__device__ __forceinline__ void F2UP(u64 v, float& a, float& b) {
    asm("mov.b64 {%0, %1}, %2;" : "=f"(a), "=f"(b) : "l"(v));
}
__device__ __forceinline__ u64 F2DUPLO(u64 v) {
    u64 r;
    asm("{ .reg .f32 lo, hi;\n\t"
        "  mov.b64 {lo, hi}, %1;\n\t"
        "  mov.b64 %0, {lo, lo}; }"
        : "=l"(r) : "l"(v));
    return r;
}

__device__ __forceinline__ void emit_row(
    const u64 hL[5], const u64 hT[5], const u64 hB[5],
    const u64 hU[4], const u64 hD[4],
    const float imv[4], float res[4])
{
    #pragma unroll
    for (int vc = 0; vc < 4; ++vc) {
        const float im = imv[vc];
        float a, b;
        // g = (sumA - n)*im + sumB ; reference order L,R,U,D then NW,NE,SW,SE
        F2UP(hL[vc],   a, b); float g0 = fmaf(a, im, b);   // L
        F2UP(hL[vc+1], a, b); float g1 = fmaf(a, im, b);   // R
        F2UP(hU[vc],   a, b); float g2 = fmaf(a, im, b);   // U
        F2UP(hD[vc],   a, b); float g3 = fmaf(a, im, b);   // D
        F2UP(hT[vc],   a, b); float h0 = fmaf(a, im, b);   // NW
        F2UP(hT[vc+1], a, b); float h1 = fmaf(a, im, b);   // NE
        F2UP(hB[vc],   a, b); float h2 = fmaf(a, im, b);   // SW
        F2UP(hB[vc+1], a, b); float h3 = fmaf(a, im, b);   // SE

        float e0 = fabsf(g0), e1 = fabsf(g1), e2 = fabsf(g2), e3 = fabsf(g3);
        float d6 = fminf(fminf(e0, e1), fminf(e2, e3));
        float b6 = (e0 == d6) ? g0 : (e1 == d6) ? g1 : (e2 == d6) ? g2 : g3;

        float f0 = fabsf(h0), f1 = fabsf(h1), f2 = fabsf(h2), f3 = fabsf(h3);
        float d4 = fminf(fminf(f0, f1), fminf(f2, f3));
        float b4 = (f0 == d4) ? h0 : (f1 == d4) ? h1 : (f2 == d4) ? h2 : h3;

        // |g4|/4 < |g6|/6  <=>  3*d4 < 2*d6 (tie -> /6 group, reference order)
        float v6 = fmaf(b6, 1.0f / 6.0f, im);
        float v4 = fmaf(b4, 0.25f, im);
        float val = (3.0f * d4 < 2.0f * d6) ? v4 : v6;
        res[vc] = fminf(fmaxf(truncf(val), 0.0f), 255.0f);
    }
}

__global__ __launch_bounds__(256, 4)
void fgf_kernel(const float* __restrict__ lrx,
                const float* __restrict__ lry,
                float* __restrict__ out,
                int H, int W)
{
    __shared__ __align__(16) float sxyE[34 * SEW];   // (x,y) pairs, even cols
    __shared__ __align__(16) float sxyO[34 * SEW];   // (x,y) pairs, odd cols
    __shared__ __align__(16) float sabE[32 * SAEW];  // (A,b) pairs, even cols
    __shared__ __align__(16) float sabO[32 * SAEW];  // (A,b) pairs, odd cols

    const int tid = threadIdx.x;
    const int c   = blockIdx.z;
    const int gx0 = blockIdx.x * TW;
    const int gy0 = blockIdx.y * TH;
    const float* __restrict__ px = lrx + (size_t)c * H * W;
    const float* __restrict__ py = lry + (size_t)c * H * W;

    const bool xin = (gx0 >= 2) && (gx0 + TW + 2 <= W);
    const bool yin = (gy0 >= 2) && (gy0 + TH + 2 <= H);
    const bool inner = xin && yin;

    // ---- stage 1: load 34x66 halo tile into (x,y) even/odd planes ----
    if (xin) {
        const int warp = tid >> 5;
        const int lane = tid & 31;
        #pragma unroll
        for (int it = 0; it < 4; ++it) {
            int r  = warp + it * 8;
            int gy = gy0 + r - 2; gy = max(0, min(H - 1, gy));
            const float* rowx = px + (size_t)gy * W + (gx0 - 2);
            const float* rowy = py + (size_t)gy * W + (gx0 - 2);
            float2 vx = *(const float2*)(rowx + lane * 2);
            float2 vy = *(const float2*)(rowy + lane * 2);
            *(float2*)&sxyE[r * SEW + lane * 2] = make_float2(vx.x, vy.x);
            *(float2*)&sxyO[r * SEW + lane * 2] = make_float2(vx.y, vy.y);
            if (lane == 31) {   // 33rd pair: cols 64,65
                float2 wx = *(const float2*)(rowx + 64);
                float2 wy = *(const float2*)(rowy + 64);
                *(float2*)&sxyE[r * SEW + 64] = make_float2(wx.x, wy.x);
                *(float2*)&sxyO[r * SEW + 64] = make_float2(wx.y, wy.y);
            }
        }
        if (warp < 2) {
            int r  = 32 + warp;
            int gy = gy0 + r - 2; gy = max(0, min(H - 1, gy));
            const float* rowx = px + (size_t)gy * W + (gx0 - 2);
            const float* rowy = py + (size_t)gy * W + (gx0 - 2);
            float2 vx = *(const float2*)(rowx + lane * 2);
            float2 vy = *(const float2*)(rowy + lane * 2);
            *(float2*)&sxyE[r * SEW + lane * 2] = make_float2(vx.x, vy.x);
            *(float2*)&sxyO[r * SEW + lane * 2] = make_float2(vx.y, vy.y);
            if (lane == 31) {
                float2 wx = *(const float2*)(rowx + 64);
                float2 wy = *(const float2*)(rowy + 64);
                *(float2*)&sxyE[r * SEW + 64] = make_float2(wx.x, wy.x);
                *(float2*)&sxyO[r * SEW + 64] = make_float2(wx.y, wy.y);
            }
        }
    } else {
        for (int i = tid; i < 34 * 66; i += 256) {
            int r = i / 66;
            int q = i - r * 66;
            int gy = gy0 + r - 2; gy = max(0, min(H - 1, gy));
            int gx = gx0 + q - 2; gx = max(0, min(W - 1, gx));
            size_t g = (size_t)gy * W + gx;
            float* plane = (q & 1) ? sxyO : sxyE;
            int off = r * SEW + (q & ~1);
            plane[off]     = px[g];
            plane[off + 1] = py[g];
        }
    }
    __syncthreads();

    // ---- stage 2: A,b on exact 32x64 grid, one 2x4 chunk per thread, packed stats ----
    {
        const int cr = tid >> 4;          // 0..15
        const int cq = tid & 15;          // 0..15
        const int r0 = cr * 2, q0 = cq * 4;
        const int fo = cq * 4;            // float offset in E/O planes

        u64 S0p[4], S0m[4], S1p[4], S1m[4];   // p=(sx,sy), m=(sxx,sxy)

        #pragma unroll
        for (int u = 0; u < 4; ++u) {
            const float* eb = &sxyE[(r0 + u) * SEW + fo];
            const float* ob = &sxyO[(r0 + u) * SEW + fo];
            ulonglong2 eL = *(const ulonglong2*)eb;
            u64 e2 = *(const u64*)(eb + 4);
            ulonglong2 oL = *(const ulonglong2*)ob;
            u64 o2 = *(const u64*)(ob + 4);
            u64 p[6] = { eL.x, oL.x, eL.y, oL.y, e2, o2 };   // cols q0..q0+5

            u64 m[6];
            #pragma unroll
            for (int v = 0; v < 6; ++v)
                m[v] = F2MUL(F2DUPLO(p[v]), p[v]);           // (x*x, x*y)

            u64 hp[4], hm[4];
            #pragma unroll
            for (int d = 0; d < 4; ++d) {
                hp[d] = F2ADD(F2ADD(p[d], p[d + 1]), p[d + 2]);
                hm[d] = F2ADD(F2ADD(m[d], m[d + 1]), m[d + 2]);
            }

            if (u == 0) {
                #pragma unroll
                for (int d = 0; d < 4; ++d) { S0p[d] = hp[d]; S0m[d] = hm[d]; }
            } else if (u == 1) {
                #pragma unroll
                for (int d = 0; d < 4; ++d) {
                    S0p[d] = F2ADD(S0p[d], hp[d]); S0m[d] = F2ADD(S0m[d], hm[d]);
                    S1p[d] = hp[d];                S1m[d] = hm[d];
                }
            } else if (u == 2) {
                #pragma unroll
                for (int d = 0; d < 4; ++d) {
                    S0p[d] = F2ADD(S0p[d], hp[d]); S0m[d] = F2ADD(S0m[d], hm[d]);
                    S1p[d] = F2ADD(S1p[d], hp[d]); S1m[d] = F2ADD(S1m[d], hm[d]);
                }
            } else {
                #pragma unroll
                for (int d = 0; d < 4; ++d) {
                    S1p[d] = F2ADD(S1p[d], hp[d]); S1m[d] = F2ADD(S1m[d], hm[d]);
                }
            }
        }

        // A = (sxy - sx*sy/9)/(sxx - sx*sx/9 + 9*eps); b = (sy - A*sx)/9
        #define COMPUTE_AB(dr, dc, A, B) { \
            float sxv, syv, sxx, sxy_; \
            F2UP((dr) ? S1p[dc] : S0p[dc], sxv, syv); \
            F2UP((dr) ? S1m[dc] : S0m[dc], sxx, sxy_); \
            float t   = sxv * (-1.0f / 9.0f); \
            float num = fmaf(t, syv, sxy_); \
            float den = fmaf(t, sxv, sxx) + 9e-4f; \
            A = __fdividef(num, den); \
            B = (syv - A * sxv) * (1.0f / 9.0f); }

        if (inner) {
            // hot path: no bounds math at all
            #pragma unroll
            for (int dr = 0; dr < 2; ++dr) {
                float Ao[4], Bo[4];
                #pragma unroll
                for (int dc = 0; dc < 4; ++dc) COMPUTE_AB(dr, dc, Ao[dc], Bo[dc]);
                *(float4*)&sabE[(r0 + dr) * SAEW + fo] = make_float4(Ao[0], Bo[0], Ao[2], Bo[2]);
                *(float4*)&sabO[(r0 + dr) * SAEW + fo] = make_float4(Ao[1], Bo[1], Ao[3], Bo[3]);
            }
        } else {
            #pragma unroll
            for (int dr = 0; dr < 2; ++dr) {
                float Ao[4], Bo[4];
                #pragma unroll
                for (int dc = 0; dc < 4; ++dc) {
                    float A, B;
                    COMPUTE_AB(dr, dc, A, B);
                    int gy = gy0 + r0 + dr - 1;
                    int gx = gx0 + q0 + dc - 1;
                    if (gy < 0 || gy >= H || gx < 0 || gx >= W) { A = 0.0f; B = 0.0f; }
                    Ao[dc] = A; Bo[dc] = B;
                }
                *(float4*)&sabE[(r0 + dr) * SAEW + fo] = make_float4(Ao[0], Bo[0], Ao[2], Bo[2]);
                *(float4*)&sabO[(r0 + dr) * SAEW + fo] = make_float4(Ao[1], Bo[1], Ao[3], Bo[3]);
            }
        }
        #undef COMPUTE_AB
    }
    __syncthreads();

    // ---- stage 3: packed (A,b) sums + cross-row reuse + grouped argmin ----
    const int maxy = min(TH, H - gy0);
    const int maxx = min(TW, W - gx0);
    const int ty  = tid >> 4;        // 0..15
    const int tx  = tid & 15;        // 0..15
    const int oy0 = ty * 2, ox0 = tx * 4;
    const int fo  = tx * 4;          // float offset in E/O planes

    if (oy0 >= maxy || ox0 >= maxx) return;   // no syncs after this point

    float* __restrict__ po = out + (size_t)c * H * W;

    #define LOADAB(C, row) { \
        const float* e_ = &sabE[(row) * SAEW + fo]; \
        const float* o_ = &sabO[(row) * SAEW + fo]; \
        ulonglong2 eL_ = *(const ulonglong2*)e_; \
        ulonglong2 oL_ = *(const ulonglong2*)o_; \
        C[0] = eL_.x; C[1] = oL_.x; C[2] = eL_.y; C[3] = oL_.y; \
        C[4] = *(const u64*)(e_ + 4); C[5] = *(const u64*)(o_ + 4); }

    #define STOREROW(oy, res) { \
        float* prow = po + (size_t)(gy0 + (oy)) * W + (gx0 + ox0); \
        if (ox0 + 4 <= maxx) { \
            *(float2*)prow       = make_float2(res[0], res[1]); \
            *(float2*)(prow + 2) = make_float2(res[2], res[3]); \
        } else { \
            _Pragma("unroll") \
            for (int vc = 0; vc < 4; ++vc) \
                if (ox0 + vc < maxx) prow[vc] = res[vc]; \
        } }

    // im values for output row oy: x components at cols ox0+2..ox0+5
    #define LOADIM(imv, oy) { \
        const float* e_ = &sxyE[((oy) + 2) * SEW + fo + 2]; \
        const float* o_ = &sxyO[((oy) + 2) * SEW + fo + 2]; \
        imv[0] = ((const float2*)e_)->x; \
        imv[1] = ((const float2*)o_)->x; \
        imv[2] = ((const float2*)(e_ + 2))->x; \
        imv[3] = ((const float2*)(o_ + 2))->x; }

    const u64 C6 = F2PK(-6.0f, 0.0f);
    const u64 C4 = F2PK(-4.0f, 0.0f);
    const u64 C2 = F2PK(-2.0f, 0.0f);

    u64 vpB[6];                    // bottom vertical pairs (live into row1)
    u64 hB[5], hD[4];              // bottom h-sums (renamed into row1's top)
    {
        u64 R0[6], R1[6], R2[6];
        LOADAB(R0, oy0);
        LOADAB(R1, oy0 + 1);
        LOADAB(R2, oy0 + 2);

        u64 vpT[6], vt[6];
        #pragma unroll
        for (int v = 0; v < 6; ++v) {
            vpT[v] = F2ADD(R0[v], R1[v]);
            vpB[v] = F2ADD(R1[v], R2[v]);
            vt[v]  = F2ADD(vpT[v], R2[v]);
        }

        u64 hL[5], hT[5], hU[4];
        #pragma unroll
        for (int q = 0; q < 5; ++q) {
            hL[q] = F2ADD(F2ADD(vt[q],  vt[q + 1]),  C6);
            hT[q] = F2ADD(F2ADD(vpT[q], vpT[q + 1]), C4);
            hB[q] = F2ADD(F2ADD(vpB[q], vpB[q + 1]), C4);
        }
        #pragma unroll
        for (int q = 0; q < 4; ++q) {
            hU[q] = F2ADD(F2ADD(hT[q], vpT[q + 2]), C2);
            hD[q] = F2ADD(F2ADD(hB[q], vpB[q + 2]), C2);
        }

        float imv[4], res[4];
        LOADIM(imv, oy0);
        emit_row(hL, hT, hB, hU, hD, imv, res);
        STOREROW(oy0, res);
    }

    // ---- row 1 (reuses: hT = row0's hB, hU = row0's hD; vpT = row0's vpB) ----
    if (oy0 + 1 < maxy) {
        u64 R2[6], R3[6];
        LOADAB(R2, oy0 + 2);
        LOADAB(R3, oy0 + 3);

        u64 vpB1[6], vt1[6];
        #pragma unroll
        for (int v = 0; v < 6; ++v) {
            vpB1[v] = F2ADD(R2[v], R3[v]);
            vt1[v]  = F2ADD(vpB[v], R3[v]);   // vpT(row1) == vpB(row0)
        }

        u64 hL1[5], hB1[5], hD1[4];
        #pragma unroll
        for (int q = 0; q < 5; ++q) {
            hL1[q] = F2ADD(F2ADD(vt1[q],  vt1[q + 1]),  C6);
            hB1[q] = F2ADD(F2ADD(vpB1[q], vpB1[q + 1]), C4);
        }
        #pragma unroll
        for (int q = 0; q < 4; ++q)
            hD1[q] = F2ADD(F2ADD(hB1[q], vpB1[q + 2]), C2);

        float imv[4], res[4];
        LOADIM(imv, oy0 + 1);
        emit_row(hL1, hB, hB1, hD, hD1, imv, res);
        STOREROW(oy0 + 1, res);
    }
    #undef LOADAB
    #undef STOREROW
    #undef LOADIM
}

extern "C" void kernel_launch(void* const* d_in, const int* in_sizes, int n_in,
                              void* d_out, int out_size)
{
    const float* lrx = (const float*)d_in[0];
    const float* lry = (const float*)d_in[1];
    // d_in[2] (hr_x) is unused by the reference computation.
    float* out = (float*)d_out;

    const int H = 2048, W = 2048;
    dim3 block(256);
    dim3 grid((W + TW - 1) / TW, (H + TH - 1) / TH, 3);
    fgf_kernel<<<grid, block>>>(lrx, lry, out, H, W);
}